// round 4
// baseline (speedup 1.0000x reference)
#include <cuda_runtime.h>
#include <cstdint>

// MultiLevelEmbedding: out[b,t,:] = emb_tables[level_ids[b,t], token_ids[b,t], :]
//                                   + level_embed[level_ids[b,t], :]
// B=64, T=1024, L=4, VOCAB=258, D=512 (float32).
//
// R4: engine-driven copy. Prologue fuses level_embed into a 2.1 MB __device__
// table (L2-resident). Main kernel: 1 warp per block orchestrates 16 rows:
//   lanes 0-15: cp.async.bulk GMEM->SMEM, 2048 B each (gathered row)
//   mbarrier expect_tx 32 KB, wait
//   lane 0: one cp.async.bulk SMEM->GMEM of 32 KB (16 output rows are
//           contiguous), commit + wait_group 0.
// No LDG/STG data path -> L1tex bypassed, no per-128B warp issue cost.

#define D_VEC     128                 // float4 per row (D=512)
#define ROW_BYTES 2048
#define VOCAB_SZ  258
#define L_LVL     4
#define N_POS     (64 * 1024)
#define ROWS_PER_BLK 16
#define BLK_BYTES (ROWS_PER_BLK * ROW_BYTES)   // 32768
#define FUSED_N   (L_LVL * VOCAB_SZ * D_VEC)   // 132096 float4 = 2.1 MB

__device__ float4 g_fused[FUSED_N];

__global__ __launch_bounds__(256)
void fuse_kernel(const float4* __restrict__ emb_tables,
                 const float4* __restrict__ level_embed) {
    const int i   = blockIdx.x * 256 + threadIdx.x;  // covers FUSED_N exactly
    const int c   = i & (D_VEC - 1);
    const int row = i >> 7;
    const int l   = row / VOCAB_SZ;

    const float4 a = __ldg(emb_tables + i);
    const float4 b = __ldg(level_embed + l * D_VEC + c);
    float4 r;
    r.x = a.x + b.x; r.y = a.y + b.y; r.z = a.z + b.z; r.w = a.w + b.w;
    g_fused[i] = r;
}

__device__ __forceinline__ uint32_t smem_u32(const void* p) {
    uint32_t a;
    asm("{ .reg .u64 t; cvta.to.shared.u64 t, %1; cvt.u32.u64 %0, t; }"
        : "=r"(a) : "l"(p));
    return a;
}

__global__ __launch_bounds__(32)
void gather_kernel(const void* __restrict__ level_ids_raw,
                   const void* __restrict__ token_ids_raw,
                   char* __restrict__ out) {
    __shared__ __align__(128) char buf[BLK_BYTES];
    __shared__ __align__(8)  unsigned long long mbar;

    const int lane = threadIdx.x;
    const uint32_t mbar_a = smem_u32(&mbar);
    const uint32_t buf_a  = smem_u32(buf);

    if (lane == 0) {
        asm volatile("mbarrier.init.shared.b64 [%0], %1;"
                     :: "r"(mbar_a), "r"(1) : "memory");
    }
    __syncwarp();

    // ---- dtype detection: odd 32-bit words of token_ids all zero <=> int64
    // (values < 258; P(false positive on int32 data) ~ (1/258)^32 ~ 0) ----
    const uint32_t* tr = (const uint32_t*)token_ids_raw;
    const unsigned nz  = __ballot_sync(0xffffffffu, tr[2 * lane + 1] != 0u);
    const bool is64    = (nz == 0u);

    if (lane == 0) {
        asm volatile("mbarrier.arrive.expect_tx.shared.b64 _, [%0], %1;"
                     :: "r"(mbar_a), "r"((uint32_t)BLK_BYTES) : "memory");
    }

    // ---- lanes 0-15: per-row index load + engine gather into smem ----
    if (lane < ROWS_PER_BLK) {
        const int pos = blockIdx.x * ROWS_PER_BLK + lane;
        long long lid, tid;
        if (is64) {
            lid = ((const long long*)level_ids_raw)[pos];
            tid = ((const long long*)token_ids_raw)[pos];
        } else {
            lid = ((const int*)level_ids_raw)[pos];
            tid = ((const int*)token_ids_raw)[pos];
        }
        const char* src = (const char*)g_fused + (lid * VOCAB_SZ + tid) * ROW_BYTES;
        asm volatile(
            "cp.async.bulk.shared::cta.global.mbarrier::complete_tx::bytes "
            "[%0], [%1], %2, [%3];"
            :: "r"(buf_a + lane * ROW_BYTES), "l"(src),
               "r"((uint32_t)ROW_BYTES), "r"(mbar_a)
            : "memory");
    }

    // ---- wait for all 32 KB to land ----
    {
        uint32_t done;
        asm volatile(
            "{\n\t.reg .pred p;\n\t"
            "mbarrier.try_wait.parity.shared.b64 p, [%1], 0;\n\t"
            "selp.b32 %0, 1, 0, p;\n\t}"
            : "=r"(done) : "r"(mbar_a) : "memory");
        while (!done) {
            asm volatile(
                "{\n\t.reg .pred p;\n\t"
                "mbarrier.try_wait.parity.shared.b64 p, [%1], 0, 0x989680;\n\t"
                "selp.b32 %0, 1, 0, p;\n\t}"
                : "=r"(done) : "r"(mbar_a) : "memory");
        }
    }

    // ---- one 32 KB engine store: 16 contiguous output rows ----
    if (lane == 0) {
        char* dst = out + (long long)blockIdx.x * BLK_BYTES;
        asm volatile(
            "cp.async.bulk.global.shared::cta.bulk_group [%0], [%1], %2;"
            :: "l"(dst), "r"(buf_a), "r"((uint32_t)BLK_BYTES) : "memory");
        asm volatile("cp.async.bulk.commit_group;" ::: "memory");
        asm volatile("cp.async.bulk.wait_group 0;" ::: "memory");
    }
    __syncwarp();
}

extern "C" void kernel_launch(void* const* d_in, const int* in_sizes, int n_in,
                              void* d_out, int out_size) {
    const void*   level_ids  = d_in[0];
    const void*   token_ids  = d_in[1];
    const float4* emb_tables = (const float4*)d_in[2];
    const float4* level_emb  = (const float4*)d_in[3];

    fuse_kernel<<<FUSED_N / 256, 256>>>(emb_tables, level_emb);
    gather_kernel<<<N_POS / ROWS_PER_BLK, 32>>>(level_ids, token_ids,
                                                (char*)d_out);
}